// round 7
// baseline (speedup 1.0000x reference)
#include <cuda_runtime.h>
#include <cstdint>

// Problem: hidden[1024], enc[65536,1024], W[1024,1024], b[1024]
// out[65536] = softmax(enc @ (W^T @ hidden) + b.hidden)
// b.hidden is a constant shift -> softmax-invariant -> dropped.

#define H 1024
#define S 65536
#define NSPLIT 16              // row splits for v partials
#define ROWS_PER_BLK 64        // K2: rows per block
#define NBLK (S / ROWS_PER_BLK)       // 1024
#define EXP_BLOCKS 64          // K3/K4: 64 blocks * 256 thr * 4 elems = 65536

// ---- device scratch (no allocation allowed) ----
__device__ __align__(16) float g_vpart[NSPLIT * H];
__device__ __align__(16) float g_v[H];
__device__ unsigned g_maxu;
__device__ float g_psum[EXP_BLOCKS];

// monotonic float->uint encoding (order-preserving for all finite floats)
__device__ __forceinline__ unsigned enc_ord(float f) {
    unsigned u = __float_as_uint(f);
    return (u & 0x80000000u) ? ~u : (u | 0x80000000u);
}
__device__ __forceinline__ float dec_ord(unsigned u) {
    return (u & 0x80000000u) ? __uint_as_float(u ^ 0x80000000u)
                             : __uint_as_float(~u);
}

// ---- K1a: partial v[j] = sum over a 64-row slab of W[i][j]*h[i] ----
// grid (H/256, NSPLIT), block 256
__global__ __launch_bounds__(256) void v_partial_kernel(
    const float* __restrict__ W, const float* __restrict__ h) {
    int col = blockIdx.x * 256 + threadIdx.x;
    int i0 = blockIdx.y * (H / NSPLIT);
    float acc = 0.f;
#pragma unroll 8
    for (int i = 0; i < H / NSPLIT; i++) {
        acc = fmaf(W[(size_t)(i0 + i) * H + col], __ldg(&h[i0 + i]), acc);
    }
    g_vpart[blockIdx.y * H + col] = acc;
}

// ---- K1b: reduce partials (deterministic order) + reset global max ----
// grid H/256, block 256
__global__ __launch_bounds__(256) void v_reduce_kernel() {
    int col = blockIdx.x * 256 + threadIdx.x;
    float s = 0.f;
#pragma unroll
    for (int k = 0; k < NSPLIT; k++) s += g_vpart[k * H + col];
    g_v[col] = s;
    if (col == 0) g_maxu = 0u;   // encoding floor (< any finite float)
}

// ---- K2: scores[s] = enc[s] . v ; track global max via atomicMax ----
// grid NBLK, block 256 (8 warps, 8 rows per warp)
__global__ __launch_bounds__(256) void scores_kernel(
    const float* __restrict__ enc, float* __restrict__ out) {
    __shared__ __align__(16) float vs[H];
    __shared__ float sscore[ROWS_PER_BLK];
    __shared__ float wmax[8];

    int tid = threadIdx.x;
    ((float4*)vs)[tid] = ((const float4*)g_v)[tid];   // 256*16B = 4KB
    __syncthreads();

    int warp = tid >> 5, lane = tid & 31;
    int row0 = blockIdx.x * ROWS_PER_BLK + warp * (ROWS_PER_BLK / 8);
    const float4* enc4 = (const float4*)enc;
    const float4* vs4 = (const float4*)vs;

    float lmax = -3.402823466e38f;
#pragma unroll
    for (int r = 0; r < ROWS_PER_BLK / 8; r++) {
        const float4* p = enc4 + (size_t)(row0 + r) * (H / 4) + lane;
        float acc = 0.f;
#pragma unroll
        for (int k = 0; k < 8; k++) {
            float4 e = __ldcs(p + k * 32);        // streaming, no L2 pollute
            float4 vv = vs4[k * 32 + lane];
            acc = fmaf(e.x, vv.x, acc);
            acc = fmaf(e.y, vv.y, acc);
            acc = fmaf(e.z, vv.z, acc);
            acc = fmaf(e.w, vv.w, acc);
        }
#pragma unroll
        for (int o = 16; o > 0; o >>= 1)
            acc += __shfl_xor_sync(0xffffffffu, acc, o);
        lmax = fmaxf(lmax, acc);                  // same value in all lanes
        if (lane == 0) sscore[warp * (ROWS_PER_BLK / 8) + r] = acc;
    }
    if (lane == 0) wmax[warp] = lmax;
    __syncthreads();

    if (tid < ROWS_PER_BLK)
        out[blockIdx.x * ROWS_PER_BLK + tid] = sscore[tid];  // coalesced

    if (tid == 0) {
        float m = wmax[0];
#pragma unroll
        for (int w = 1; w < 8; w++) m = fmaxf(m, wmax[w]);
        atomicMax(&g_maxu, enc_ord(m));   // order-invariant -> deterministic
    }
}

// ---- K3: e = exp(s - max); per-block partial sums (deterministic tree) ----
// grid EXP_BLOCKS, block 256, 4 elems/thread
__global__ __launch_bounds__(256) void exp_kernel(float* __restrict__ out) {
    __shared__ float red[256];
    int tid = threadIdx.x;
    int idx = blockIdx.x * 256 + tid;
    float gmax = dec_ord(g_maxu);
    float4 s = ((float4*)out)[idx];
    s.x = __expf(s.x - gmax);
    s.y = __expf(s.y - gmax);
    s.z = __expf(s.z - gmax);
    s.w = __expf(s.w - gmax);
    ((float4*)out)[idx] = s;
    red[tid] = (s.x + s.y) + (s.z + s.w);
    __syncthreads();
#pragma unroll
    for (int o = 128; o > 0; o >>= 1) {
        if (tid < o) red[tid] += red[tid + o];
        __syncthreads();
    }
    if (tid == 0) g_psum[blockIdx.x] = red[0];
}

// ---- K4: total = sum(g_psum) (fixed serial order), scale ----
__global__ __launch_bounds__(256) void norm_kernel(float* __restrict__ out) {
    __shared__ float sinv;
    int tid = threadIdx.x;
    if (tid == 0) {
        float s = 0.f;
#pragma unroll
        for (int k = 0; k < EXP_BLOCKS; k++) s += g_psum[k];
        sinv = 1.0f / s;
    }
    __syncthreads();
    float inv = sinv;
    int idx = blockIdx.x * 256 + tid;
    float4 v = ((float4*)out)[idx];
    v.x *= inv; v.y *= inv; v.z *= inv; v.w *= inv;
    ((float4*)out)[idx] = v;
}

extern "C" void kernel_launch(void* const* d_in, const int* in_sizes, int n_in,
                              void* d_out, int out_size) {
    const float* hidden = (const float*)d_in[0];  // [1024]
    const float* enc    = (const float*)d_in[1];  // [65536,1024]
    const float* W      = (const float*)d_in[2];  // [1024,1024]
    // d_in[3] = b : unused (softmax shift-invariant)
    float* out = (float*)d_out;                   // [65536]

    v_partial_kernel<<<dim3(H / 256, NSPLIT), 256>>>(W, hidden);
    v_reduce_kernel<<<H / 256, 256>>>();
    scores_kernel<<<NBLK, 256>>>(enc, out);
    exp_kernel<<<EXP_BLOCKS, 256>>>(out);
    norm_kernel<<<EXP_BLOCKS, 256>>>(out);
}

// round 12
// speedup vs baseline: 1.0203x; 1.0203x over previous
#include <cuda_runtime.h>
#include <cstdint>

// hidden[1024], enc[65536,1024], W[1024,1024], b[1024]
// out[65536] = softmax(enc @ (W^T @ hidden) + b.hidden)
// b.hidden is a uniform shift across scores -> softmax-invariant -> dropped.

#define H 1024
#define S 65536
#define NSPLIT 16               // K1: row slabs
#define ROWS_PER_BLK 64         // K2: rows per block
#define NBLK (S / ROWS_PER_BLK) // 1024
#define EXP_BLOCKS 64           // K3: 64 blocks * 256 thr * float4 = 65536

// ---- device scratch (no allocation allowed) ----
__device__ __align__(16) float g_vpart[NSPLIT * H];
__device__ __align__(16) float g_v[H];
__device__ unsigned g_maxu;
__device__ float g_psum[EXP_BLOCKS];
__device__ int g_c1 = 0;   // K1 arrival counter (reset by K2 for next replay)
__device__ int g_c3 = 0;   // K3 arrival counter (reset by K1 each replay)

// monotonic float<->uint encoding (order-preserving)
__device__ __forceinline__ unsigned enc_ord(float f) {
    unsigned u = __float_as_uint(f);
    return (u & 0x80000000u) ? ~u : (u | 0x80000000u);
}
__device__ __forceinline__ float dec_ord(unsigned u) {
    return (u & 0x80000000u) ? __uint_as_float(u ^ 0x80000000u)
                             : __uint_as_float(~u);
}

// ============ K1: v = W^T h, fused partial + reduce (grid-resident spin) ====
// grid (H/256, NSPLIT) = 64 blocks (single wave on 148 SMs), block 256
__global__ __launch_bounds__(256) void v_kernel(
    const float* __restrict__ W, const float* __restrict__ h) {
    int tid = threadIdx.x;
    int col = blockIdx.x * 256 + tid;
    int i0 = blockIdx.y * (H / NSPLIT);
    float acc = 0.f;
#pragma unroll 8
    for (int i = 0; i < H / NSPLIT; i++)
        acc = fmaf(W[(size_t)(i0 + i) * H + col], __ldg(&h[i0 + i]), acc);
    g_vpart[blockIdx.y * H + col] = acc;

    __syncthreads();
    if (tid == 0) {
        __threadfence();
        atomicAdd(&g_c1, 1);
    }
    if (blockIdx.y != 0) return;

    // reduction blocks (4 of them) wait for all 64 slabs
    if (tid == 0) {
        while (*(volatile int*)&g_c1 < (H / 256) * NSPLIT) __nanosleep(32);
        __threadfence();
    }
    __syncthreads();
    float s = 0.f;
#pragma unroll
    for (int k = 0; k < NSPLIT; k++) s += g_vpart[k * H + col];
    g_v[col] = s;
    if (col == 0) { g_maxu = 0u; g_c3 = 0; }  // resets for K2/K3 this replay
}

// ============ K2: scores = enc . v  + global max ============================
// grid NBLK, block 256: 8 warps x 8 rows; per-lane partials -> padded smem,
// deterministic serial reduce in phase 2 (NO shuffles inside the load loop,
// full unroll so ptxas can front-batch independent LDG.128s => high MLP).
__global__ __launch_bounds__(256) void scores_kernel(
    const float* __restrict__ enc, float* __restrict__ out) {
    __shared__ __align__(16) float vs[H];
    __shared__ float part[ROWS_PER_BLK * 33];   // stride-33 pad: conflict-free
    __shared__ float wmax[2];

    int tid = threadIdx.x;
    ((float4*)vs)[tid] = ((const float4*)g_v)[tid];
    if (blockIdx.x == 0 && tid == 0) g_c1 = 0;  // reset for next replay's K1
    __syncthreads();

    int warp = tid >> 5, lane = tid & 31;
    int row0 = blockIdx.x * ROWS_PER_BLK + warp * 8;
    const float4* enc4 = (const float4*)enc;
    const float4* vs4 = (const float4*)vs;

#pragma unroll
    for (int r = 0; r < 8; r++) {
        const float4* p = enc4 + (size_t)(row0 + r) * (H / 4) + lane;
        float acc = 0.f;
#pragma unroll
        for (int k = 0; k < 8; k++) {
            float4 e = __ldcs(p + k * 32);       // streaming: no L2 pollute
            float4 vv = vs4[k * 32 + lane];
            acc = fmaf(e.x, vv.x, acc);
            acc = fmaf(e.y, vv.y, acc);
            acc = fmaf(e.z, vv.z, acc);
            acc = fmaf(e.w, vv.w, acc);
        }
        part[(warp * 8 + r) * 33 + lane] = acc;  // no reduce in load loop
    }
    __syncthreads();

    if (tid < ROWS_PER_BLK) {
        float s = 0.f;
#pragma unroll
        for (int k = 0; k < 32; k++) s += part[tid * 33 + k];  // deterministic
        out[blockIdx.x * ROWS_PER_BLK + tid] = s;              // coalesced
        float m = s;
#pragma unroll
        for (int o = 16; o > 0; o >>= 1)
            m = fmaxf(m, __shfl_xor_sync(0xffffffffu, m, o));
        if (lane == 0) wmax[tid >> 5] = m;
    }
    __syncthreads();
    if (tid == 0)
        atomicMax(&g_maxu, enc_ord(fmaxf(wmax[0], wmax[1])));  // order-invariant
}

// ============ K3: exp + global-sum + normalize, one kernel ==================
// grid 64 (single wave -> spin barrier safe), block 256, float4/thread.
// exp'd values stay in registers across the barrier: saves a 256KB re-read
// and an entire launch vs a split exp/normalize pair.
__global__ __launch_bounds__(256) void softmax_kernel(float* __restrict__ out) {
    __shared__ float wsum[8];
    __shared__ float sinv;
    int tid = threadIdx.x;
    int idx = blockIdx.x * 256 + tid;
    float gmax = dec_ord(g_maxu);

    float4 s = ((float4*)out)[idx];
    s.x = __expf(s.x - gmax);
    s.y = __expf(s.y - gmax);
    s.z = __expf(s.z - gmax);
    s.w = __expf(s.w - gmax);

    float l = (s.x + s.y) + (s.z + s.w);
#pragma unroll
    for (int o = 16; o > 0; o >>= 1)
        l += __shfl_xor_sync(0xffffffffu, l, o);
    if ((tid & 31) == 0) wsum[tid >> 5] = l;
    __syncthreads();

    if (tid == 0) {
        float b = 0.f;
#pragma unroll
        for (int w = 0; w < 8; w++) b += wsum[w];
        g_psum[blockIdx.x] = b;
        __threadfence();
        atomicAdd(&g_c3, 1);
        while (*(volatile int*)&g_c3 < EXP_BLOCKS) __nanosleep(32);
        __threadfence();
        float t = 0.f;
#pragma unroll
        for (int k = 0; k < EXP_BLOCKS; k++) t += g_psum[k];  // deterministic
        sinv = 1.0f / t;
    }
    __syncthreads();

    float inv = sinv;
    s.x *= inv; s.y *= inv; s.z *= inv; s.w *= inv;
    ((float4*)out)[idx] = s;
}

extern "C" void kernel_launch(void* const* d_in, const int* in_sizes, int n_in,
                              void* d_out, int out_size) {
    const float* hidden = (const float*)d_in[0];  // [1024]
    const float* enc    = (const float*)d_in[1];  // [65536,1024]
    const float* W      = (const float*)d_in[2];  // [1024,1024]
    // d_in[3] = b : unused (softmax shift-invariant)
    float* out = (float*)d_out;                   // [65536]

    v_kernel<<<dim3(H / 256, NSPLIT), 256>>>(W, hidden);
    scores_kernel<<<NBLK, 256>>>(enc, out);
    softmax_kernel<<<EXP_BLOCKS, 256>>>(out);
}